// round 1
// baseline (speedup 1.0000x reference)
#include <cuda_runtime.h>
#include <math.h>

// Problem dims
#define NB 1024
#define NT 64
#define ND 256
#define NL 256
#define NC 256
#define NH 1024
#define EPSV 1e-7f
#define LOG2PI 1.8378770664093453f
#define BETAV (1.0f/3.0f)

// ---------------- scratch (device globals; no allocation allowed) -------------
__device__ __align__(16) float g_y1[(size_t)NB * NT * NH];        // 256 MB
__device__ __align__(16) float g_ctx[(size_t)NB * NT * (NC + ND)]; // 128 MB
__device__ __align__(16) float g_zs[(size_t)NB * NT * NL];         // 64 MB  (B,T,L)
__device__ __align__(16) float g_zc[NB * (NL + NC + ND)];          // (B,768): [z | c_t]
__device__ __align__(16) float g_hf[NB * NH];
__device__ __align__(16) float g_hh[NB * NH];
__device__ __align__(16) float g_drift[NB * NL];
__device__ __align__(16) float g_prior[NB * NL];
__device__ __align__(16) float g_q[NB * 2 * NL];
__device__ float g_dkl[NB];
__device__ float g_kl0[NB];
__device__ float g_diffv[NL];
__device__ float g_partials[4096];

// ---------------- helpers -----------------------------------------------------
__device__ __forceinline__ float block_reduce_sum_256(float v, float* sh) {
    int tid = threadIdx.x;
    sh[tid] = v;
    __syncthreads();
    #pragma unroll
    for (int s = 128; s > 0; s >>= 1) {
        if (tid < s) sh[tid] += sh[tid + s];
        __syncthreads();
    }
    float r = sh[0];
    __syncthreads();
    return r;
}

// ---------------- generic tiled fp32 GEMM: C = act(A@W + bias) ----------------
// A: [M,K] row-major with leading dim lda; W: [K,N] row-major (ld = N);
// C: [M,N] with leading dim ldc. Tiles: 64x64x16, 256 threads, 4x4/thread.
// M%64==0, N%64==0, K%16==0, lda%4==0 (all hold for this problem).
#define BM 64
#define BN 64
#define BKT 16

template<int TANH>
__global__ __launch_bounds__(256)
void gemm_k(const float* __restrict__ A, int lda,
            const float* __restrict__ W,
            const float* __restrict__ bias,
            float* __restrict__ C, int ldc,
            int M, int N, int K)
{
    __shared__ float As[BKT][BM];
    __shared__ float Bs[BKT][BN];

    const int bm = blockIdx.y * BM;
    const int bn = blockIdx.x * BN;
    const int tid = threadIdx.x;
    const int tx = tid & 15;          // 0..15 -> 4 cols each
    const int ty = tid >> 4;          // 0..15 -> 4 rows each

    // A tile loader: am in 0..63, ak in {0,4,8,12}
    const int am = tid >> 2;
    const int ak = (tid & 3) << 2;
    // B tile loader: bkr in 0..15, bnc in {0,4,...,60}
    const int bkr = tid >> 4;
    const int bnc = (tid & 15) << 2;

    const float* Aptr = A + (size_t)(bm + am) * lda + ak;
    const float* Wptr = W + (size_t)bkr * N + bn + bnc;

    float acc[4][4];
    #pragma unroll
    for (int i = 0; i < 4; i++)
        #pragma unroll
        for (int j = 0; j < 4; j++) acc[i][j] = 0.f;

    for (int k0 = 0; k0 < K; k0 += BKT) {
        float4 av = *reinterpret_cast<const float4*>(Aptr + k0);
        float4 wv = *reinterpret_cast<const float4*>(Wptr + (size_t)k0 * N);
        As[ak + 0][am] = av.x;
        As[ak + 1][am] = av.y;
        As[ak + 2][am] = av.z;
        As[ak + 3][am] = av.w;
        *reinterpret_cast<float4*>(&Bs[bkr][bnc]) = wv;
        __syncthreads();

        #pragma unroll
        for (int kk = 0; kk < BKT; kk++) {
            float4 bv = *reinterpret_cast<const float4*>(&Bs[kk][tx << 2]);
            float a0 = As[kk][(ty << 2) + 0];
            float a1 = As[kk][(ty << 2) + 1];
            float a2 = As[kk][(ty << 2) + 2];
            float a3 = As[kk][(ty << 2) + 3];
            acc[0][0] += a0 * bv.x; acc[0][1] += a0 * bv.y; acc[0][2] += a0 * bv.z; acc[0][3] += a0 * bv.w;
            acc[1][0] += a1 * bv.x; acc[1][1] += a1 * bv.y; acc[1][2] += a1 * bv.z; acc[1][3] += a1 * bv.w;
            acc[2][0] += a2 * bv.x; acc[2][1] += a2 * bv.y; acc[2][2] += a2 * bv.z; acc[2][3] += a2 * bv.w;
            acc[3][0] += a3 * bv.x; acc[3][1] += a3 * bv.y; acc[3][2] += a3 * bv.z; acc[3][3] += a3 * bv.w;
        }
        __syncthreads();
    }

    #pragma unroll
    for (int i = 0; i < 4; i++) {
        int row = bm + (ty << 2) + i;
        #pragma unroll
        for (int j = 0; j < 4; j++) {
            int col = bn + (tx << 2) + j;
            float v = acc[i][j] + bias[col];
            if (TANH) v = tanhf(v);
            C[(size_t)row * ldc + col] = v;
        }
    }
}

// ---- decoder GEMM fused with Gaussian NLL partial reduction ------------------
// A = zs [65536,256] (B,T,L) row-major; W = proj_w [256,256]; xs [65536,256].
// partials[block] = sum over tile of -0.5*((xs - x_hat)/std)^2
__global__ __launch_bounds__(256)
void gemm_logpx_k(const float* __restrict__ A,
                  const float* __restrict__ W,
                  const float* __restrict__ bias,
                  const float* __restrict__ xs,
                  const float* __restrict__ nstd_p,
                  float* __restrict__ partials)
{
    __shared__ float As[BKT][BM];
    __shared__ float Bs[BKT][BN];
    __shared__ float sred[256];

    const int M = NB * NT, N = ND, K = NL;
    const int bm = blockIdx.y * BM;
    const int bn = blockIdx.x * BN;
    const int tid = threadIdx.x;
    const int tx = tid & 15;
    const int ty = tid >> 4;
    const int am = tid >> 2;
    const int ak = (tid & 3) << 2;
    const int bkr = tid >> 4;
    const int bnc = (tid & 15) << 2;

    const float* Aptr = A + (size_t)(bm + am) * K + ak;
    const float* Wptr = W + (size_t)bkr * N + bn + bnc;

    float acc[4][4];
    #pragma unroll
    for (int i = 0; i < 4; i++)
        #pragma unroll
        for (int j = 0; j < 4; j++) acc[i][j] = 0.f;

    for (int k0 = 0; k0 < K; k0 += BKT) {
        float4 av = *reinterpret_cast<const float4*>(Aptr + k0);
        float4 wv = *reinterpret_cast<const float4*>(Wptr + (size_t)k0 * N);
        As[ak + 0][am] = av.x;
        As[ak + 1][am] = av.y;
        As[ak + 2][am] = av.z;
        As[ak + 3][am] = av.w;
        *reinterpret_cast<float4*>(&Bs[bkr][bnc]) = wv;
        __syncthreads();
        #pragma unroll
        for (int kk = 0; kk < BKT; kk++) {
            float4 bv = *reinterpret_cast<const float4*>(&Bs[kk][tx << 2]);
            float a0 = As[kk][(ty << 2) + 0];
            float a1 = As[kk][(ty << 2) + 1];
            float a2 = As[kk][(ty << 2) + 2];
            float a3 = As[kk][(ty << 2) + 3];
            acc[0][0] += a0 * bv.x; acc[0][1] += a0 * bv.y; acc[0][2] += a0 * bv.z; acc[0][3] += a0 * bv.w;
            acc[1][0] += a1 * bv.x; acc[1][1] += a1 * bv.y; acc[1][2] += a1 * bv.z; acc[1][3] += a1 * bv.w;
            acc[2][0] += a2 * bv.x; acc[2][1] += a2 * bv.y; acc[2][2] += a2 * bv.z; acc[2][3] += a2 * bv.w;
            acc[3][0] += a3 * bv.x; acc[3][1] += a3 * bv.y; acc[3][2] += a3 * bv.z; acc[3][3] += a3 * bv.w;
        }
        __syncthreads();
    }

    float inv_std = 1.f / nstd_p[0];
    float local = 0.f;
    #pragma unroll
    for (int i = 0; i < 4; i++) {
        int row = bm + (ty << 2) + i;
        #pragma unroll
        for (int j = 0; j < 4; j++) {
            int col = bn + (tx << 2) + j;
            float xh = acc[i][j] + bias[col];
            float r = (xs[(size_t)row * ND + col] - xh) * inv_std;
            local += r * r;
        }
    }
    float s = block_reduce_sum_256(local, sred);
    if (tid == 0) partials[blockIdx.y * gridDim.x + blockIdx.x] = -0.5f * s;
    (void)M; (void)N;
}

// ---------------- small elementwise / setup kernels ---------------------------
__global__ void copy_xs_ctx_k(const float* __restrict__ xs, float* __restrict__ ctx) {
    size_t i = (size_t)blockIdx.x * 256 + threadIdx.x;   // over B*T*D
    size_t bt = i / ND, d = i % ND;
    ctx[bt * (NC + ND) + NC + d] = xs[i];
}

__global__ void diffv_k(const float* __restrict__ gamma, float* __restrict__ diffv) {
    int l = threadIdx.x;
    diffv[l] = sqrtf(2.f / (BETAV * gamma[l]));
}

__global__ void z0_k(const float* __restrict__ q, const float* __restrict__ eps0,
                     const float* __restrict__ pm, const float* __restrict__ pl,
                     float* __restrict__ zc, float* __restrict__ zs,
                     float* __restrict__ kl0, float* __restrict__ dkl)
{
    __shared__ float sh[256];
    int b = blockIdx.x, l = threadIdx.x;
    float qm = q[b * 512 + l];
    float ql = q[b * 512 + 256 + l];
    float z0 = qm + expf(ql) * eps0[b * NL + l];
    zc[b * 768 + l] = z0;
    zs[(size_t)b * NT * NL + l] = z0;
    float pmv = pm[l], plv = pl[l];
    float dm = qm - pmv;
    float term = plv - ql + (expf(2.f * ql) + dm * dm) / (2.f * expf(2.f * plv)) - 0.5f;
    float s = block_reduce_sum_256(term, sh);
    if (l == 0) { kl0[b] = s; dkl[b] = 0.f; }
}

__global__ void copy_ct_k(int t, const float* __restrict__ ctx, float* __restrict__ zc) {
    int i = blockIdx.x * 256 + threadIdx.x;  // over B*512
    int b = i >> 9, j = i & 511;
    zc[b * 768 + 256 + j] = ctx[((size_t)b * NT + (t + 1)) * 512 + j];
}

__global__ void step_k(int t, const float* __restrict__ ts,
                       const float* __restrict__ noise,
                       float* __restrict__ zc, float* __restrict__ zs,
                       const float* __restrict__ drift, const float* __restrict__ prior,
                       const float* __restrict__ diffv, float* __restrict__ dkl)
{
    __shared__ float sh[256];
    int b = blockIdx.x, l = threadIdx.x;
    float dt = ts[t + 1] - ts[t];
    float sqdt = sqrtf(dt);
    float d = drift[b * NL + l];
    float p = prior[b * NL + l];
    float df = diffv[l];
    float sgn = (float)((df > 0.f) - (df < 0.f));
    float den = fabsf(df) > EPSV ? df : sgn * EPSV;
    float r = (d - p) / den;
    float rate = block_reduce_sum_256(r * r, sh);
    float z = zc[b * 768 + l];
    float e = noise[((size_t)t * NB + b) * NL + l];
    float zn = z + d * dt + df * sqdt * e;
    zc[b * 768 + l] = zn;
    zs[((size_t)b * NT + (t + 1)) * NL + l] = zn;
    if (l == 0) dkl[b] += rate * dt;
}

__global__ void finalize_k(const float* __restrict__ partials, int np,
                           const float* __restrict__ dkl, const float* __restrict__ kl0,
                           const float* __restrict__ nstd_p, float* __restrict__ out)
{
    __shared__ float sh[256];
    int tid = threadIdx.x;
    float s = 0.f;
    for (int i = tid; i < np; i += 256) s += partials[i];
    float tot = block_reduce_sum_256(s, sh);

    float s2 = 0.f;
    for (int i = tid; i < NB; i += 256) s2 += dkl[i];
    float dkl_tot = block_reduce_sum_256(s2, sh);

    float s3 = 0.f;
    for (int i = tid; i < NB; i += 256) s3 += kl0[i];
    float kl0_tot = block_reduce_sum_256(s3, sh);

    if (tid == 0) {
        float nstd = nstd_p[0];
        float cst = (float)NT * (float)ND * (-logf(nstd) - 0.5f * LOG2PI);
        float log_pxs = tot / (float)NB + cst;
        out[0] = -log_pxs;
        out[1] = dkl_tot / (float)NB + kl0_tot / (float)NB;
    }
}

// ---------------- launch ------------------------------------------------------
extern "C" void kernel_launch(void* const* d_in, const int* in_sizes, int n_in,
                              void* d_out, int out_size)
{
    const float* xs        = (const float*)d_in[0];
    const float* ts        = (const float*)d_in[1];
    const float* noise_std = (const float*)d_in[2];
    const float* eps0      = (const float*)d_in[3];
    const float* noise     = (const float*)d_in[4];
    const float* enc_w1    = (const float*)d_in[5];
    const float* enc_b1    = (const float*)d_in[6];
    const float* enc_w2    = (const float*)d_in[7];
    const float* enc_b2    = (const float*)d_in[8];
    const float* qz0_w     = (const float*)d_in[9];
    const float* qz0_b     = (const float*)d_in[10];
    const float* f_w1      = (const float*)d_in[11];
    const float* f_b1      = (const float*)d_in[12];
    const float* f_w2      = (const float*)d_in[13];
    const float* f_b2      = (const float*)d_in[14];
    const float* h_w1      = (const float*)d_in[15];
    const float* h_b1      = (const float*)d_in[16];
    const float* h_w2      = (const float*)d_in[17];
    const float* h_b2      = (const float*)d_in[18];
    const float* proj_w    = (const float*)d_in[19];
    const float* proj_b    = (const float*)d_in[20];
    const float* pz0_mean  = (const float*)d_in[21];
    const float* pz0_logstd= (const float*)d_in[22];
    const float* gamma     = (const float*)d_in[23];

    float *y1, *ctx, *zs, *zc, *hf, *hh, *drift, *prior, *q, *dkl, *kl0, *diffv, *partials;
    cudaGetSymbolAddress((void**)&y1, g_y1);
    cudaGetSymbolAddress((void**)&ctx, g_ctx);
    cudaGetSymbolAddress((void**)&zs, g_zs);
    cudaGetSymbolAddress((void**)&zc, g_zc);
    cudaGetSymbolAddress((void**)&hf, g_hf);
    cudaGetSymbolAddress((void**)&hh, g_hh);
    cudaGetSymbolAddress((void**)&drift, g_drift);
    cudaGetSymbolAddress((void**)&prior, g_prior);
    cudaGetSymbolAddress((void**)&q, g_q);
    cudaGetSymbolAddress((void**)&dkl, g_dkl);
    cudaGetSymbolAddress((void**)&kl0, g_kl0);
    cudaGetSymbolAddress((void**)&diffv, g_diffv);
    cudaGetSymbolAddress((void**)&partials, g_partials);

    const int M = NB * NT;

    // Encoder: y1 = tanh(xs @ enc_w1 + b1); enc = y1 @ enc_w2 + b2 -> ctx[:, :, 0:256]
    gemm_k<1><<<dim3(NH / BN, M / BM), 256>>>(xs, ND, enc_w1, enc_b1, y1, NH, M, NH, ND);
    gemm_k<0><<<dim3(NC / BN, M / BM), 256>>>(y1, NH, enc_w2, enc_b2, ctx, NC + ND, M, NC, NH);
    copy_xs_ctx_k<<<(size_t)M * ND / 256, 256>>>(xs, ctx);

    // q = ctx[:,0,:] @ qz0_w + qz0_b  (lda = T*512)
    gemm_k<0><<<dim3(512 / BN, NB / BM), 256>>>(ctx, NT * 512, qz0_w, qz0_b, q, 512, NB, 512, 512);

    z0_k<<<NB, 256>>>(q, eps0, pz0_mean, pz0_logstd, zc, zs, kl0, dkl);
    diffv_k<<<1, NL>>>(gamma, diffv);

    for (int t = 0; t < NT - 1; t++) {
        copy_ct_k<<<(NB * 512) / 256, 256>>>(t, ctx, zc);
        // hidden_f = tanh([z|c_t] @ f_w1 + f_b1)   (K=768)
        gemm_k<1><<<dim3(NH / BN, NB / BM), 256>>>(zc, 768, f_w1, f_b1, hf, NH, NB, NH, 768);
        // hidden_h = tanh(z @ h_w1 + h_b1)          (K=256, same zc, lda=768)
        gemm_k<1><<<dim3(NH / BN, NB / BM), 256>>>(zc, 768, h_w1, h_b1, hh, NH, NB, NH, NL);
        // drift = hidden_f @ f_w2 + f_b2
        gemm_k<0><<<dim3(NL / BN, NB / BM), 256>>>(hf, NH, f_w2, f_b2, drift, NL, NB, NL, NH);
        // prior = hidden_h @ h_w2 + h_b2
        gemm_k<0><<<dim3(NL / BN, NB / BM), 256>>>(hh, NH, h_w2, h_b2, prior, NL, NB, NL, NH);
        step_k<<<NB, 256>>>(t, ts, noise, zc, zs, drift, prior, diffv, dkl);
    }

    // x_hat = zs @ proj_w + proj_b fused with -0.5*((xs-x_hat)/std)^2 reduction
    gemm_logpx_k<<<dim3(ND / BN, M / BM), 256>>>(zs, proj_w, proj_b, xs, noise_std, partials);

    finalize_k<<<1, 256>>>(partials, (M / BM) * (ND / BN), dkl, kl0, noise_std, (float*)d_out);

    (void)in_sizes; (void)n_in; (void)out_size;
}

// round 4
// speedup vs baseline: 3.4567x; 3.4567x over previous
#include <cuda_runtime.h>
#include <math.h>
#include <stdint.h>

// ---------------- problem dims ------------------------------------------------
#define NB 1024
#define NT 64
#define ND 256
#define NL 256
#define NH 1024
#define EPSV 1e-7f
#define LOG2PI 1.8378770664093453f
#define BETAV (1.0f/3.0f)

// ---------------- scratch (device globals) ------------------------------------
__device__ __align__(16) float g_y1[(size_t)NB * NT * NH];     // 256 MB
__device__ __align__(16) float g_ctx[(size_t)NB * NT * 512];   // 128 MB (rounded)
__device__ __align__(16) float g_xst[(size_t)NB * NT * ND];    // 64 MB (rounded xs)
__device__ __align__(16) float g_zs[(size_t)NB * NT * NL];     // 64 MB (rounded)
__device__ __align__(16) float g_z[NB * NL];                   // exact z state
__device__ __align__(16) float g_zct[NB * 768];                // rounded [z | c_t]
__device__ __align__(16) float g_hf[NB * NH];
__device__ __align__(16) float g_hh[NB * NH];
__device__ __align__(16) float g_drift[NB * NL];
__device__ __align__(16) float g_prior[NB * NL];
__device__ __align__(16) float g_q[NB * 512];
__device__ __align__(16) float g_wt[2424832];                  // rounded weights
__device__ float g_dkl[NB];
__device__ float g_kl0[NB];
__device__ float g_diffv[NL];
__device__ float g_partials[4096];

// weight offsets in g_wt (floats)
#define W_ENC1 0
#define W_ENC2 262144
#define W_QZ0  524288
#define W_F1   786432
#define W_F2   1572864
#define W_H1   1835008
#define W_H2   2097152
#define W_PROJ 2359296

// ---------------- helpers -----------------------------------------------------
__device__ __forceinline__ uint32_t s2u(const void* p) {
    uint32_t a;
    asm("{ .reg .u64 t; cvta.to.shared.u64 t, %1; cvt.u32.u64 %0, t; }" : "=r"(a) : "l"(p));
    return a;
}
__device__ __forceinline__ void cp16(uint32_t saddr, const void* g) {
    asm volatile("cp.async.cg.shared.global [%0], [%1], 16;" :: "r"(saddr), "l"(g));
}
__device__ __forceinline__ float frnd(float x) {
    uint32_t u;
    asm("cvt.rna.tf32.f32 %0, %1;" : "=r"(u) : "f"(x));
    return __uint_as_float(u);
}
__device__ __forceinline__ void mma_tf32(float* c, uint32_t a0, uint32_t a1, uint32_t a2, uint32_t a3,
                                         uint32_t b0, uint32_t b1) {
    asm volatile("mma.sync.aligned.m16n8k8.row.col.f32.tf32.tf32.f32 "
                 "{%0,%1,%2,%3},{%4,%5,%6,%7},{%8,%9},{%0,%1,%2,%3};"
                 : "+f"(c[0]), "+f"(c[1]), "+f"(c[2]), "+f"(c[3])
                 : "r"(a0), "r"(a1), "r"(a2), "r"(a3), "r"(b0), "r"(b1));
}
__device__ __forceinline__ float block_reduce_sum_256(float v, float* sh) {
    int tid = threadIdx.x;
    sh[tid] = v;
    __syncthreads();
    #pragma unroll
    for (int s = 128; s > 0; s >>= 1) {
        if (tid < s) sh[tid] += sh[tid + s];
        __syncthreads();
    }
    float r = sh[0];
    __syncthreads();
    return r;
}

// ---------------- tensor-core GEMM via mma.sync tf32 --------------------------
// C = act(A @ W + bias). Dual-group: blockIdx.y < mSplit -> g0, else g1.
// A [M,K] row-major (lda), W [K,N] row-major (ldw), C [M,N] (ldc).
// Tile: BMT x 128 x 32. 256 threads = 8 warps (2 rows x 4 cols),
// warp tile (BMT/2) x 32. 2-stage cp.async pipeline.
// As [BMT][36], Bs [32][136] (both conflict-free for the fragment patterns).
// RND: round output to tf32 (it feeds another GEMM). EPI: fused NLL reduction.
struct GArgs {
    const float* A; int lda;
    const float* W; int ldw;
    const float* bias;
    float* C; int ldc;
    int K;
};

template<int BMT, int ACT, int RND, int EPI>
__global__ void __launch_bounds__(256)
gemm_mma(GArgs g0, GArgs g1, int mSplit,
         const float* __restrict__ xs, const float* __restrict__ nstd_p,
         float* __restrict__ partials)
{
    extern __shared__ char smem[];
    constexpr int MT  = BMT / 32;          // m16-tiles per warp
    constexpr int ASZ = BMT * 36;          // floats per A stage
    constexpr int BSZ = 32 * 136;
    constexpr int STG = ASZ + BSZ;

    const int tid  = threadIdx.x;
    const int wid  = tid >> 5;
    const int lane = tid & 31;
    const int lr   = lane >> 2;            // 0..7
    const int lc   = lane & 3;             // 0..3

    const bool grp1 = ((int)blockIdx.y >= mSplit);
    const GArgs g = grp1 ? g1 : g0;
    const int bm = (grp1 ? ((int)blockIdx.y - mSplit) : (int)blockIdx.y) * BMT;
    const int bn = (int)blockIdx.x * 128;

    float* s0 = (float*)smem;
    const uint32_t sbase = s2u(smem);

    const int warpM = (wid >> 2) * (BMT / 2);
    const int warpN = (wid & 3) * 32;

    auto loadtile = [&](int s, int c) {
        const int k0 = c << 5;
        uint32_t sA = sbase + (uint32_t)(s * STG) * 4u;
        uint32_t sB = sA + (uint32_t)ASZ * 4u;
        const float* Ag = g.A + (size_t)bm * g.lda + k0;
        #pragma unroll
        for (int i = 0; i < BMT / 32; i++) {
            int idx = tid + (i << 8);
            int m = idx >> 3, k4 = (idx & 7) << 2;
            cp16(sA + (uint32_t)(m * 36 + k4) * 4u, Ag + (size_t)m * g.lda + k4);
        }
        const float* Wg = g.W + (size_t)k0 * g.ldw + bn;
        #pragma unroll
        for (int i = 0; i < 4; i++) {
            int idx = tid + (i << 8);
            int k = idx >> 5, n4 = (idx & 31) << 2;
            cp16(sB + (uint32_t)(k * 136 + n4) * 4u, Wg + (size_t)k * g.ldw + n4);
        }
        asm volatile("cp.async.commit_group;" ::: "memory");
    };

    float acc[MT][4][4];
    #pragma unroll
    for (int mt = 0; mt < MT; mt++)
        #pragma unroll
        for (int nt = 0; nt < 4; nt++)
            #pragma unroll
            for (int r = 0; r < 4; r++) acc[mt][nt][r] = 0.f;

    const int nch = g.K >> 5;
    loadtile(0, 0);
    if (nch > 1) loadtile(1, 1);

    for (int c = 0; c < nch; c++) {
        if (c + 1 < nch) asm volatile("cp.async.wait_group 1;" ::: "memory");
        else             asm volatile("cp.async.wait_group 0;" ::: "memory");
        __syncthreads();

        const float* As = s0 + (c & 1) * STG;
        const float* Bs = As + ASZ;

        #pragma unroll
        for (int ks = 0; ks < 4; ks++) {
            const int k8 = ks * 8;
            uint32_t b[4][2];
            #pragma unroll
            for (int nt = 0; nt < 4; nt++) {
                b[nt][0] = __float_as_uint(Bs[(k8 + lc) * 136 + warpN + nt * 8 + lr]);
                b[nt][1] = __float_as_uint(Bs[(k8 + lc + 4) * 136 + warpN + nt * 8 + lr]);
            }
            #pragma unroll
            for (int mt = 0; mt < MT; mt++) {
                const int r0 = warpM + mt * 16 + lr;
                uint32_t a0 = __float_as_uint(As[r0 * 36 + k8 + lc]);
                uint32_t a1 = __float_as_uint(As[(r0 + 8) * 36 + k8 + lc]);
                uint32_t a2 = __float_as_uint(As[r0 * 36 + k8 + lc + 4]);
                uint32_t a3 = __float_as_uint(As[(r0 + 8) * 36 + k8 + lc + 4]);
                #pragma unroll
                for (int nt = 0; nt < 4; nt++)
                    mma_tf32(acc[mt][nt], a0, a1, a2, a3, b[nt][0], b[nt][1]);
            }
        }
        __syncthreads();
        if (c + 2 < nch) loadtile(c & 1, c + 2);
    }

    // ---- epilogue ----
    float loc = 0.f;
    const float invs = EPI ? (1.f / nstd_p[0]) : 0.f;
    #pragma unroll
    for (int mt = 0; mt < MT; mt++) {
        const int row0 = bm + warpM + mt * 16 + lr;
        #pragma unroll
        for (int nt = 0; nt < 4; nt++) {
            const int col = bn + warpN + nt * 8 + lc * 2;
            float2 bb = *reinterpret_cast<const float2*>(g.bias + col);
            float v00 = acc[mt][nt][0] + bb.x;
            float v01 = acc[mt][nt][1] + bb.y;
            float v10 = acc[mt][nt][2] + bb.x;
            float v11 = acc[mt][nt][3] + bb.y;
            if (ACT) { v00 = tanhf(v00); v01 = tanhf(v01); v10 = tanhf(v10); v11 = tanhf(v11); }
            if (RND) { v00 = frnd(v00); v01 = frnd(v01); v10 = frnd(v10); v11 = frnd(v11); }
            if (EPI == 0) {
                *reinterpret_cast<float2*>(g.C + (size_t)row0 * g.ldc + col) = make_float2(v00, v01);
                *reinterpret_cast<float2*>(g.C + (size_t)(row0 + 8) * g.ldc + col) = make_float2(v10, v11);
            } else {
                float2 x0 = *reinterpret_cast<const float2*>(xs + (size_t)row0 * g.ldc + col);
                float2 x1 = *reinterpret_cast<const float2*>(xs + (size_t)(row0 + 8) * g.ldc + col);
                float r0 = (x0.x - v00) * invs, r1 = (x0.y - v01) * invs;
                float r2 = (x1.x - v10) * invs, r3 = (x1.y - v11) * invs;
                loc += r0 * r0 + r1 * r1 + r2 * r2 + r3 * r3;
            }
        }
    }
    if (EPI) {
        __syncthreads();   // stages no longer needed; reuse as reduction buffer
        float tot = block_reduce_sum_256(loc, s0);
        if (tid == 0) partials[blockIdx.y * gridDim.x + blockIdx.x] = -0.5f * tot;
    }
}

// ---------------- small kernels -----------------------------------------------
__global__ void rnd_copy_k(const float* __restrict__ s, float* __restrict__ d, int n) {
    int i = blockIdx.x * 256 + threadIdx.x;
    if (i < n) d[i] = frnd(s[i]);
}

__global__ void copy_xs_k(const float* __restrict__ xs, float* __restrict__ ctx,
                          float* __restrict__ xst) {
    size_t i = (size_t)blockIdx.x * 256 + threadIdx.x;   // over B*T*256
    size_t bt = i >> 8, d = i & 255;
    float v = frnd(xs[i]);
    ctx[bt * 512 + 256 + d] = v;
    xst[i] = v;
}

__global__ void diffv_k(const float* __restrict__ gamma, float* __restrict__ diffv) {
    int l = threadIdx.x;
    diffv[l] = sqrtf(2.f / (BETAV * gamma[l]));
}

__global__ void z0_k(const float* __restrict__ q, const float* __restrict__ eps0,
                     const float* __restrict__ pm, const float* __restrict__ pl,
                     float* __restrict__ z, float* __restrict__ zct, float* __restrict__ zs,
                     float* __restrict__ kl0, float* __restrict__ dkl)
{
    __shared__ float sh[256];
    int b = blockIdx.x, l = threadIdx.x;
    float qm = q[b * 512 + l];
    float ql = q[b * 512 + 256 + l];
    float z0 = qm + expf(ql) * eps0[b * NL + l];
    z[b * NL + l] = z0;
    float zr = frnd(z0);
    zct[b * 768 + l] = zr;
    zs[(size_t)b * NT * NL + l] = zr;
    float pmv = pm[l], plv = pl[l];
    float dm = qm - pmv;
    float term = plv - ql + (expf(2.f * ql) + dm * dm) / (2.f * expf(2.f * plv)) - 0.5f;
    float s = block_reduce_sum_256(term, sh);
    if (l == 0) { kl0[b] = s; dkl[b] = 0.f; }
}

__global__ void copy_ct_k(const float* __restrict__ ctx, float* __restrict__ zct) {
    int i = blockIdx.x * 256 + threadIdx.x;  // over B*512, t=1
    int b = i >> 9, j = i & 511;
    zct[b * 768 + 256 + j] = ctx[((size_t)b * NT + 1) * 512 + j];
}

__global__ void step_k(int t, const float* __restrict__ ts,
                       const float* __restrict__ noise,
                       const float* __restrict__ ctx,
                       float* __restrict__ z, float* __restrict__ zct, float* __restrict__ zs,
                       const float* __restrict__ drift, const float* __restrict__ prior,
                       const float* __restrict__ diffv, float* __restrict__ dkl)
{
    __shared__ float sh[256];
    int b = blockIdx.x, l = threadIdx.x;
    float dt = ts[t + 1] - ts[t];
    float sqdt = sqrtf(dt);
    float d = drift[b * NL + l];
    float p = prior[b * NL + l];
    float df = diffv[l];
    float sgn = (float)((df > 0.f) - (df < 0.f));
    float den = fabsf(df) > EPSV ? df : sgn * EPSV;
    float r = (d - p) / den;
    float rate = block_reduce_sum_256(r * r, sh);
    float zv = z[b * NL + l];
    float e = noise[((size_t)t * NB + b) * NL + l];
    float zn = zv + d * dt + df * sqdt * e;
    z[b * NL + l] = zn;
    float zr = frnd(zn);
    zct[b * 768 + l] = zr;
    zs[((size_t)b * NT + (t + 1)) * NL + l] = zr;
    if (l == 0) dkl[b] += rate * dt;
    // stage c_{t+2} for next step's GEMMs (ctx already tf32-rounded)
    if (t + 2 <= NT - 1) {
        int j0 = l << 1;
        #pragma unroll
        for (int u = 0; u < 2; u++) {
            int j = j0 + u;
            zct[b * 768 + 256 + j] = ctx[((size_t)b * NT + (t + 2)) * 512 + j];
        }
    }
}

__global__ void finalize_k(const float* __restrict__ partials, int np,
                           const float* __restrict__ dkl, const float* __restrict__ kl0,
                           const float* __restrict__ nstd_p, float* __restrict__ out)
{
    __shared__ float sh[256];
    int tid = threadIdx.x;
    float s = 0.f;
    for (int i = tid; i < np; i += 256) s += partials[i];
    float tot = block_reduce_sum_256(s, sh);

    float s2 = 0.f;
    for (int i = tid; i < NB; i += 256) s2 += dkl[i];
    float dkl_tot = block_reduce_sum_256(s2, sh);

    float s3 = 0.f;
    for (int i = tid; i < NB; i += 256) s3 += kl0[i];
    float kl0_tot = block_reduce_sum_256(s3, sh);

    if (tid == 0) {
        float nstd = nstd_p[0];
        float cst = (float)NT * (float)ND * (-logf(nstd) - 0.5f * LOG2PI);
        float log_pxs = tot / (float)NB + cst;
        out[0] = -log_pxs;
        out[1] = dkl_tot / (float)NB + kl0_tot / (float)NB;
    }
}

// ---------------- launch ------------------------------------------------------
#define SMEM128 (2 * (128*36 + 32*136) * 4)   // 71680
#define SMEM64  (2 * (64*36 + 32*136) * 4)    // 53248

extern "C" void kernel_launch(void* const* d_in, const int* in_sizes, int n_in,
                              void* d_out, int out_size)
{
    const float* xs        = (const float*)d_in[0];
    const float* ts        = (const float*)d_in[1];
    const float* noise_std = (const float*)d_in[2];
    const float* eps0      = (const float*)d_in[3];
    const float* noise     = (const float*)d_in[4];
    const float* enc_w1    = (const float*)d_in[5];
    const float* enc_b1    = (const float*)d_in[6];
    const float* enc_w2    = (const float*)d_in[7];
    const float* enc_b2    = (const float*)d_in[8];
    const float* qz0_w     = (const float*)d_in[9];
    const float* qz0_b     = (const float*)d_in[10];
    const float* f_w1      = (const float*)d_in[11];
    const float* f_b1      = (const float*)d_in[12];
    const float* f_w2      = (const float*)d_in[13];
    const float* f_b2      = (const float*)d_in[14];
    const float* h_w1      = (const float*)d_in[15];
    const float* h_b1      = (const float*)d_in[16];
    const float* h_w2      = (const float*)d_in[17];
    const float* h_b2      = (const float*)d_in[18];
    const float* proj_w    = (const float*)d_in[19];
    const float* proj_b    = (const float*)d_in[20];
    const float* pz0_mean  = (const float*)d_in[21];
    const float* pz0_logstd= (const float*)d_in[22];
    const float* gamma     = (const float*)d_in[23];

    float *y1, *ctx, *xst, *zs, *z, *zct, *hf, *hh, *drift, *prior, *q, *wt;
    float *dkl, *kl0, *diffv, *partials;
    cudaGetSymbolAddress((void**)&y1, g_y1);
    cudaGetSymbolAddress((void**)&ctx, g_ctx);
    cudaGetSymbolAddress((void**)&xst, g_xst);
    cudaGetSymbolAddress((void**)&zs, g_zs);
    cudaGetSymbolAddress((void**)&z, g_z);
    cudaGetSymbolAddress((void**)&zct, g_zct);
    cudaGetSymbolAddress((void**)&hf, g_hf);
    cudaGetSymbolAddress((void**)&hh, g_hh);
    cudaGetSymbolAddress((void**)&drift, g_drift);
    cudaGetSymbolAddress((void**)&prior, g_prior);
    cudaGetSymbolAddress((void**)&q, g_q);
    cudaGetSymbolAddress((void**)&wt, g_wt);
    cudaGetSymbolAddress((void**)&dkl, g_dkl);
    cudaGetSymbolAddress((void**)&kl0, g_kl0);
    cudaGetSymbolAddress((void**)&diffv, g_diffv);
    cudaGetSymbolAddress((void**)&partials, g_partials);

    cudaFuncSetAttribute(gemm_mma<128,1,1,0>, cudaFuncAttributeMaxDynamicSharedMemorySize, SMEM128);
    cudaFuncSetAttribute(gemm_mma<128,0,1,0>, cudaFuncAttributeMaxDynamicSharedMemorySize, SMEM128);
    cudaFuncSetAttribute(gemm_mma<128,0,0,0>, cudaFuncAttributeMaxDynamicSharedMemorySize, SMEM128);
    cudaFuncSetAttribute(gemm_mma<128,0,0,1>, cudaFuncAttributeMaxDynamicSharedMemorySize, SMEM128);
    cudaFuncSetAttribute(gemm_mma<64,0,0,0>,  cudaFuncAttributeMaxDynamicSharedMemorySize, SMEM64);

    const int M = NB * NT;

    // ---- round weights to tf32 (one-time per replay, cheap) ----
    rnd_copy_k<<<(262144+255)/256, 256>>>(enc_w1, wt + W_ENC1, 262144);
    rnd_copy_k<<<(262144+255)/256, 256>>>(enc_w2, wt + W_ENC2, 262144);
    rnd_copy_k<<<(262144+255)/256, 256>>>(qz0_w,  wt + W_QZ0,  262144);
    rnd_copy_k<<<(786432+255)/256, 256>>>(f_w1,   wt + W_F1,   786432);
    rnd_copy_k<<<(262144+255)/256, 256>>>(f_w2,   wt + W_F2,   262144);
    rnd_copy_k<<<(262144+255)/256, 256>>>(h_w1,   wt + W_H1,   262144);
    rnd_copy_k<<<(262144+255)/256, 256>>>(h_w2,   wt + W_H2,   262144);
    rnd_copy_k<<<(65536+255)/256,  256>>>(proj_w, wt + W_PROJ, 65536);
    copy_xs_k<<<(int)((size_t)M * ND / 256), 256>>>(xs, ctx, xst);

    GArgs zg{};

    // ---- encoder ----
    {
        GArgs a{xst, ND, wt + W_ENC1, NH, enc_b1, y1, NH, ND};
        gemm_mma<128,1,1,0><<<dim3(NH/128, M/128), 256, SMEM128>>>(a, a, M/128, nullptr, nullptr, nullptr);
    }
    {
        GArgs a{y1, NH, wt + W_ENC2, NL, enc_b2, ctx, 512, NH};
        gemm_mma<128,0,1,0><<<dim3(NL/128, M/128), 256, SMEM128>>>(a, a, M/128, nullptr, nullptr, nullptr);
    }

    // ---- q = ctx[:,0,:] @ qz0_w + qz0_b ----
    {
        GArgs a{ctx, NT * 512, wt + W_QZ0, 512, qz0_b, q, 512, 512};
        gemm_mma<128,0,0,0><<<dim3(512/128, NB/128), 256, SMEM128>>>(a, a, NB/128, nullptr, nullptr, nullptr);
    }

    z0_k<<<NB, 256>>>(q, eps0, pz0_mean, pz0_logstd, z, zct, zs, kl0, dkl);
    diffv_k<<<1, NL>>>(gamma, diffv);
    copy_ct_k<<<(NB * 512) / 256, 256>>>(ctx, zct);

    // ---- scan: 63 steps, 3 launches each ----
    for (int t = 0; t < NT - 1; t++) {
        GArgs a0{zct, 768, wt + W_F1, NH, f_b1, hf, NH, 768};
        GArgs a1{zct, 768, wt + W_H1, NH, h_b1, hh, NH, NL};
        gemm_mma<128,1,1,0><<<dim3(NH/128, 2*(NB/128)), 256, SMEM128>>>(a0, a1, NB/128, nullptr, nullptr, nullptr);

        GArgs b0{hf, NH, wt + W_F2, NL, f_b2, drift, NL, NH};
        GArgs b1{hh, NH, wt + W_H2, NL, h_b2, prior, NL, NH};
        gemm_mma<64,0,0,0><<<dim3(NL/128, 2*(NB/64)), 256, SMEM64>>>(b0, b1, NB/64, nullptr, nullptr, nullptr);

        step_k<<<NB, 256>>>(t, ts, noise, ctx, z, zct, zs, drift, prior, diffv, dkl);
    }

    // ---- decoder fused with NLL reduction ----
    {
        GArgs a{zs, NL, wt + W_PROJ, ND, proj_b, nullptr, ND, NL};
        gemm_mma<128,0,0,1><<<dim3(ND/128, M/128), 256, SMEM128>>>(a, zg, M/128, xs, noise_std, partials);
    }

    finalize_k<<<1, 256>>>(partials, (M/128) * (ND/128), dkl, kl0, noise_std, (float*)d_out);

    (void)in_sizes; (void)n_in; (void)out_size;
}

// round 5
// speedup vs baseline: 5.8552x; 1.6939x over previous
#include <cuda_runtime.h>
#include <cuda_bf16.h>
#include <math.h>
#include <stdint.h>

// ---------------- problem dims ------------------------------------------------
#define NB 1024
#define NT 64
#define ND 256
#define NL 256
#define NH 1024
#define EPSV 1e-7f
#define LOG2PI 1.8378770664093453f
#define BETAV (1.0f/3.0f)

typedef __nv_bfloat16 bf16;

// ---------------- scratch (device globals) ------------------------------------
__device__ __align__(16) bf16  g_y1[(size_t)NB * NT * NH];     // 128 MB
__device__ __align__(16) bf16  g_ctx[(size_t)NB * NT * 512];   // 64 MB
__device__ __align__(16) bf16  g_xst[(size_t)NB * NT * ND];    // 32 MB
__device__ __align__(16) bf16  g_zs[(size_t)NB * NT * NL];     // 32 MB
__device__ __align__(16) float g_z[NB * NL];                   // exact z state
__device__ __align__(16) bf16  g_zct[NB * 768];                // [z | c_t] bf16
__device__ __align__(16) bf16  g_hf[NB * NH];
__device__ __align__(16) bf16  g_hh[NB * NH];
__device__ __align__(16) float g_drift[NB * NL];
__device__ __align__(16) float g_prior[NB * NL];
__device__ __align__(16) float g_q[NB * 512];
__device__ __align__(16) bf16  g_wtb[2424832];                 // transposed bf16 weights
__device__ float g_dkl[NB];
__device__ float g_kl0[NB];
__device__ float g_diffv[NL];
__device__ float g_partials[4096];

// weight offsets in g_wtb (elements), all stored transposed [N][K]
#define W_ENC1 0
#define W_ENC2 262144
#define W_QZ0  524288
#define W_F1   786432
#define W_F2   1572864
#define W_H1   1835008
#define W_H2   2097152
#define W_PROJ 2359296

// ---------------- helpers -----------------------------------------------------
__device__ __forceinline__ uint32_t s2u(const void* p) {
    uint32_t a;
    asm("{ .reg .u64 t; cvta.to.shared.u64 t, %1; cvt.u32.u64 %0, t; }" : "=r"(a) : "l"(p));
    return a;
}
__device__ __forceinline__ void cp16(uint32_t saddr, const void* g) {
    asm volatile("cp.async.cg.shared.global [%0], [%1], 16;" :: "r"(saddr), "l"(g));
}
__device__ __forceinline__ void mma_bf16(float* c, uint32_t a0, uint32_t a1, uint32_t a2, uint32_t a3,
                                         uint32_t b0, uint32_t b1) {
    asm volatile("mma.sync.aligned.m16n8k16.row.col.f32.bf16.bf16.f32 "
                 "{%0,%1,%2,%3},{%4,%5,%6,%7},{%8,%9},{%0,%1,%2,%3};"
                 : "+f"(c[0]), "+f"(c[1]), "+f"(c[2]), "+f"(c[3])
                 : "r"(a0), "r"(a1), "r"(a2), "r"(a3), "r"(b0), "r"(b1));
}
__device__ __forceinline__ float block_reduce_sum_256(float v, float* sh) {
    int tid = threadIdx.x;
    sh[tid] = v;
    __syncthreads();
    #pragma unroll
    for (int s = 128; s > 0; s >>= 1) {
        if (tid < s) sh[tid] += sh[tid + s];
        __syncthreads();
    }
    float r = sh[0];
    __syncthreads();
    return r;
}

// ---------------- bf16 tensor-core GEMM ---------------------------------------
// C = act(A @ Wt^T + bias). A [M,K] bf16 row-major (lda). Wt [N,K] bf16 row-major
// (transposed weight, row length = K). C [M,N]. Tile BMT x 128 x 64 (BK=64).
// 256 threads = 8 warps (2 x 4), warp tile (BMT/2) x 32.
// smem: A [BMT][72] bf16, B [128][72] bf16 (stride 72 -> conflict-free), 2 stages.
// OUTBF: store C as bf16 (feeds another GEMM). EPI: fused NLL reduction (no store).
struct GArgs {
    const bf16* A; int lda;
    const bf16* W;            // transposed [N][K], row stride = K
    const float* bias;
    void* C; int ldc;
    int K;
};

template<int BMT, int ACT, int OUTBF, int EPI>
__global__ void __launch_bounds__(256)
gemm_bf(GArgs g0, GArgs g1, int mSplit,
        const float* __restrict__ xs, const float* __restrict__ nstd_p,
        float* __restrict__ partials)
{
    extern __shared__ char smem[];
    constexpr int MT  = (BMT + 31) / 32;   // m16-tiles per warp (BMT/32)
    constexpr int ASZ = BMT * 72;          // bf16 elems per A stage
    constexpr int BSZ = 128 * 72;
    constexpr int STG = ASZ + BSZ;

    const int tid  = threadIdx.x;
    const int wid  = tid >> 5;
    const int lane = tid & 31;
    const int lr   = lane >> 2;            // 0..7
    const int lc   = lane & 3;             // 0..3

    const bool grp1 = ((int)blockIdx.y >= mSplit);
    const GArgs g = grp1 ? g1 : g0;
    const int bm = (grp1 ? ((int)blockIdx.y - mSplit) : (int)blockIdx.y) * BMT;
    const int bn = (int)blockIdx.x * 128;

    bf16* sm = (bf16*)smem;
    const uint32_t sbase = s2u(smem);

    const int warpM = (wid >> 2) * (BMT / 2);
    const int warpN = (wid & 3) * 32;

    auto loadtile = [&](int s, int c) {
        const int k0 = c << 6;
        uint32_t sA = sbase + (uint32_t)(s * STG) * 2u;
        uint32_t sB = sA + (uint32_t)ASZ * 2u;
        const bf16* Ag = g.A + (size_t)bm * g.lda + k0;
        #pragma unroll
        for (int i = 0; i < BMT / 32; i++) {
            int idx = tid + (i << 8);
            int m = idx >> 3, k8 = (idx & 7) << 3;
            cp16(sA + (uint32_t)(m * 72 + k8) * 2u, Ag + (size_t)m * g.lda + k8);
        }
        const bf16* Wg = g.W + (size_t)bn * g.K + k0;
        #pragma unroll
        for (int i = 0; i < 4; i++) {
            int idx = tid + (i << 8);
            int n = idx >> 3, k8 = (idx & 7) << 3;
            cp16(sB + (uint32_t)(n * 72 + k8) * 2u, Wg + (size_t)n * g.K + k8);
        }
        asm volatile("cp.async.commit_group;" ::: "memory");
    };

    float acc[MT][4][4];
    #pragma unroll
    for (int mt = 0; mt < MT; mt++)
        #pragma unroll
        for (int nt = 0; nt < 4; nt++)
            #pragma unroll
            for (int r = 0; r < 4; r++) acc[mt][nt][r] = 0.f;

    const int nch = g.K >> 6;
    loadtile(0, 0);
    if (nch > 1) loadtile(1, 1);

    for (int c = 0; c < nch; c++) {
        if (c + 1 < nch) asm volatile("cp.async.wait_group 1;" ::: "memory");
        else             asm volatile("cp.async.wait_group 0;" ::: "memory");
        __syncthreads();

        const bf16* As = sm + (c & 1) * STG;
        const bf16* Bs = As + ASZ;

        #pragma unroll
        for (int ks = 0; ks < 4; ks++) {
            const int kk = (ks << 4) + (lc << 1);
            uint32_t b[4][2];
            #pragma unroll
            for (int nt = 0; nt < 4; nt++) {
                const bf16* bp = Bs + (warpN + nt * 8 + lr) * 72 + kk;
                b[nt][0] = *reinterpret_cast<const uint32_t*>(bp);
                b[nt][1] = *reinterpret_cast<const uint32_t*>(bp + 8);
            }
            #pragma unroll
            for (int mt = 0; mt < MT; mt++) {
                const bf16* ap = As + (warpM + mt * 16 + lr) * 72 + kk;
                uint32_t a0 = *reinterpret_cast<const uint32_t*>(ap);
                uint32_t a1 = *reinterpret_cast<const uint32_t*>(ap + 8 * 72);
                uint32_t a2 = *reinterpret_cast<const uint32_t*>(ap + 8);
                uint32_t a3 = *reinterpret_cast<const uint32_t*>(ap + 8 * 72 + 8);
                #pragma unroll
                for (int nt = 0; nt < 4; nt++)
                    mma_bf16(acc[mt][nt], a0, a1, a2, a3, b[nt][0], b[nt][1]);
            }
        }
        __syncthreads();
        if (c + 2 < nch) loadtile(c & 1, c + 2);
    }

    // ---- epilogue ----
    float loc = 0.f;
    const float invs = EPI ? (1.f / nstd_p[0]) : 0.f;
    #pragma unroll
    for (int mt = 0; mt < MT; mt++) {
        const int row0 = bm + warpM + mt * 16 + lr;
        #pragma unroll
        for (int nt = 0; nt < 4; nt++) {
            const int col = bn + warpN + nt * 8 + (lc << 1);
            float2 bb = *reinterpret_cast<const float2*>(g.bias + col);
            float v00 = acc[mt][nt][0] + bb.x;
            float v01 = acc[mt][nt][1] + bb.y;
            float v10 = acc[mt][nt][2] + bb.x;
            float v11 = acc[mt][nt][3] + bb.y;
            if (ACT) { v00 = tanhf(v00); v01 = tanhf(v01); v10 = tanhf(v10); v11 = tanhf(v11); }
            if (EPI) {
                float2 x0 = *reinterpret_cast<const float2*>(xs + (size_t)row0 * g.ldc + col);
                float2 x1 = *reinterpret_cast<const float2*>(xs + (size_t)(row0 + 8) * g.ldc + col);
                float r0 = (x0.x - v00) * invs, r1 = (x0.y - v01) * invs;
                float r2 = (x1.x - v10) * invs, r3 = (x1.y - v11) * invs;
                loc += r0 * r0 + r1 * r1 + r2 * r2 + r3 * r3;
            } else if (OUTBF) {
                bf16* Cb = (bf16*)g.C;
                __nv_bfloat162 p0 = __floats2bfloat162_rn(v00, v01);
                __nv_bfloat162 p1 = __floats2bfloat162_rn(v10, v11);
                *reinterpret_cast<__nv_bfloat162*>(Cb + (size_t)row0 * g.ldc + col) = p0;
                *reinterpret_cast<__nv_bfloat162*>(Cb + (size_t)(row0 + 8) * g.ldc + col) = p1;
            } else {
                float* Cf = (float*)g.C;
                *reinterpret_cast<float2*>(Cf + (size_t)row0 * g.ldc + col) = make_float2(v00, v01);
                *reinterpret_cast<float2*>(Cf + (size_t)(row0 + 8) * g.ldc + col) = make_float2(v10, v11);
            }
        }
    }
    if (EPI) {
        __syncthreads();
        float tot = block_reduce_sum_256(loc, (float*)smem);
        if (tid == 0) partials[blockIdx.y * gridDim.x + blockIdx.x] = -0.5f * tot;
    }
}

// ---------------- prologue kernels --------------------------------------------
// transpose W [K,N] f32 -> Wt [N,K] bf16
__global__ void transp_k(const float* __restrict__ W, bf16* __restrict__ Wt, int K, int N) {
    __shared__ float t[32][33];
    int n0 = blockIdx.x * 32, k0 = blockIdx.y * 32;
    int tx = threadIdx.x, ty = threadIdx.y;  // 32 x 8
    #pragma unroll
    for (int j = 0; j < 4; j++)
        t[ty + j * 8][tx] = W[(size_t)(k0 + ty + j * 8) * N + n0 + tx];
    __syncthreads();
    #pragma unroll
    for (int j = 0; j < 4; j++)
        Wt[(size_t)(n0 + ty + j * 8) * K + k0 + tx] = __float2bfloat16(t[tx][ty + j * 8]);
}

__global__ void copy_xs_k(const float* __restrict__ xs, bf16* __restrict__ ctx,
                          bf16* __restrict__ xst) {
    size_t i = (size_t)blockIdx.x * 256 + threadIdx.x;   // over B*T*256
    size_t bt = i >> 8, d = i & 255;
    bf16 v = __float2bfloat16(xs[i]);
    ctx[bt * 512 + 256 + d] = v;
    xst[i] = v;
}

__global__ void diffv_k(const float* __restrict__ gamma, float* __restrict__ diffv) {
    int l = threadIdx.x;
    diffv[l] = sqrtf(2.f / (BETAV * gamma[l]));
}

__global__ void z0_k(const float* __restrict__ q, const float* __restrict__ eps0,
                     const float* __restrict__ pm, const float* __restrict__ pl,
                     float* __restrict__ z, bf16* __restrict__ zct, bf16* __restrict__ zs,
                     float* __restrict__ kl0, float* __restrict__ dkl)
{
    __shared__ float sh[256];
    int b = blockIdx.x, l = threadIdx.x;
    float qm = q[b * 512 + l];
    float ql = q[b * 512 + 256 + l];
    float z0 = qm + expf(ql) * eps0[b * NL + l];
    z[b * NL + l] = z0;
    bf16 zr = __float2bfloat16(z0);
    zct[b * 768 + l] = zr;
    zs[(size_t)b * NT * NL + l] = zr;
    float pmv = pm[l], plv = pl[l];
    float dm = qm - pmv;
    float term = plv - ql + (expf(2.f * ql) + dm * dm) / (2.f * expf(2.f * plv)) - 0.5f;
    float s = block_reduce_sum_256(term, sh);
    if (l == 0) { kl0[b] = s; dkl[b] = 0.f; }
}

__global__ void copy_ct_k(const bf16* __restrict__ ctx, bf16* __restrict__ zct) {
    int i = blockIdx.x * 256 + threadIdx.x;  // over B*512, t=1
    int b = i >> 9, j = i & 511;
    zct[b * 768 + 256 + j] = ctx[((size_t)b * NT + 1) * 512 + j];
}

__global__ void step_k(int t, const float* __restrict__ ts,
                       const float* __restrict__ noise,
                       const bf16* __restrict__ ctx,
                       float* __restrict__ z, bf16* __restrict__ zct, bf16* __restrict__ zs,
                       const float* __restrict__ drift, const float* __restrict__ prior,
                       const float* __restrict__ diffv, float* __restrict__ dkl)
{
    __shared__ float sh[256];
    int b = blockIdx.x, l = threadIdx.x;
    float dt = ts[t + 1] - ts[t];
    float sqdt = sqrtf(dt);
    float d = drift[b * NL + l];
    float p = prior[b * NL + l];
    float df = diffv[l];
    float sgn = (float)((df > 0.f) - (df < 0.f));
    float den = fabsf(df) > EPSV ? df : sgn * EPSV;
    float r = (d - p) / den;
    float rate = block_reduce_sum_256(r * r, sh);
    float zv = z[b * NL + l];
    float e = noise[((size_t)t * NB + b) * NL + l];
    float zn = zv + d * dt + df * sqdt * e;
    z[b * NL + l] = zn;
    bf16 zr = __float2bfloat16(zn);
    zct[b * 768 + l] = zr;
    zs[((size_t)b * NT + (t + 1)) * NL + l] = zr;
    if (l == 0) dkl[b] += rate * dt;
    // stage c_{t+2} for next step's GEMMs
    if (t + 2 <= NT - 1) {
        int j0 = l << 1;
        #pragma unroll
        for (int u = 0; u < 2; u++) {
            int j = j0 + u;
            zct[b * 768 + 256 + j] = ctx[((size_t)b * NT + (t + 2)) * 512 + j];
        }
    }
}

__global__ void finalize_k(const float* __restrict__ partials, int np,
                           const float* __restrict__ dkl, const float* __restrict__ kl0,
                           const float* __restrict__ nstd_p, float* __restrict__ out)
{
    __shared__ float sh[256];
    int tid = threadIdx.x;
    float s = 0.f;
    for (int i = tid; i < np; i += 256) s += partials[i];
    float tot = block_reduce_sum_256(s, sh);

    float s2 = 0.f;
    for (int i = tid; i < NB; i += 256) s2 += dkl[i];
    float dkl_tot = block_reduce_sum_256(s2, sh);

    float s3 = 0.f;
    for (int i = tid; i < NB; i += 256) s3 += kl0[i];
    float kl0_tot = block_reduce_sum_256(s3, sh);

    if (tid == 0) {
        float nstd = nstd_p[0];
        float cst = (float)NT * (float)ND * (-logf(nstd) - 0.5f * LOG2PI);
        float log_pxs = tot / (float)NB + cst;
        out[0] = -log_pxs;
        out[1] = dkl_tot / (float)NB + kl0_tot / (float)NB;
    }
}

// ---------------- launch ------------------------------------------------------
#define SMEM128 (2 * (128*72 + 128*72) * 2)   // 73728
#define SMEM32  (2 * (32*72  + 128*72) * 2)   // 46080

extern "C" void kernel_launch(void* const* d_in, const int* in_sizes, int n_in,
                              void* d_out, int out_size)
{
    const float* xs        = (const float*)d_in[0];
    const float* ts        = (const float*)d_in[1];
    const float* noise_std = (const float*)d_in[2];
    const float* eps0      = (const float*)d_in[3];
    const float* noise     = (const float*)d_in[4];
    const float* enc_w1    = (const float*)d_in[5];
    const float* enc_b1    = (const float*)d_in[6];
    const float* enc_w2    = (const float*)d_in[7];
    const float* enc_b2    = (const float*)d_in[8];
    const float* qz0_w     = (const float*)d_in[9];
    const float* qz0_b     = (const float*)d_in[10];
    const float* f_w1      = (const float*)d_in[11];
    const float* f_b1      = (const float*)d_in[12];
    const float* f_w2      = (const float*)d_in[13];
    const float* f_b2      = (const float*)d_in[14];
    const float* h_w1      = (const float*)d_in[15];
    const float* h_b1      = (const float*)d_in[16];
    const float* h_w2      = (const float*)d_in[17];
    const float* h_b2      = (const float*)d_in[18];
    const float* proj_w    = (const float*)d_in[19];
    const float* proj_b    = (const float*)d_in[20];
    const float* pz0_mean  = (const float*)d_in[21];
    const float* pz0_logstd= (const float*)d_in[22];
    const float* gamma     = (const float*)d_in[23];

    bf16 *y1, *ctx, *xst, *zs, *zct, *hf, *hh, *wtb;
    float *z, *drift, *prior, *q, *dkl, *kl0, *diffv, *partials;
    cudaGetSymbolAddress((void**)&y1, g_y1);
    cudaGetSymbolAddress((void**)&ctx, g_ctx);
    cudaGetSymbolAddress((void**)&xst, g_xst);
    cudaGetSymbolAddress((void**)&zs, g_zs);
    cudaGetSymbolAddress((void**)&z, g_z);
    cudaGetSymbolAddress((void**)&zct, g_zct);
    cudaGetSymbolAddress((void**)&hf, g_hf);
    cudaGetSymbolAddress((void**)&hh, g_hh);
    cudaGetSymbolAddress((void**)&drift, g_drift);
    cudaGetSymbolAddress((void**)&prior, g_prior);
    cudaGetSymbolAddress((void**)&q, g_q);
    cudaGetSymbolAddress((void**)&wtb, g_wtb);
    cudaGetSymbolAddress((void**)&dkl, g_dkl);
    cudaGetSymbolAddress((void**)&kl0, g_kl0);
    cudaGetSymbolAddress((void**)&diffv, g_diffv);
    cudaGetSymbolAddress((void**)&partials, g_partials);

    cudaFuncSetAttribute(gemm_bf<128,1,1,0>, cudaFuncAttributeMaxDynamicSharedMemorySize, SMEM128);
    cudaFuncSetAttribute(gemm_bf<128,0,1,0>, cudaFuncAttributeMaxDynamicSharedMemorySize, SMEM128);
    cudaFuncSetAttribute(gemm_bf<128,0,0,0>, cudaFuncAttributeMaxDynamicSharedMemorySize, SMEM128);
    cudaFuncSetAttribute(gemm_bf<128,0,0,1>, cudaFuncAttributeMaxDynamicSharedMemorySize, SMEM128);
    cudaFuncSetAttribute(gemm_bf<32,0,0,0>,  cudaFuncAttributeMaxDynamicSharedMemorySize, SMEM32);

    const int M = NB * NT;
    dim3 tb(32, 8);

    // ---- transpose + convert weights to bf16 [N][K] ----
    transp_k<<<dim3(NH/32,  ND/32), tb>>>(enc_w1, wtb + W_ENC1, ND,  NH);
    transp_k<<<dim3(NL/32,  NH/32), tb>>>(enc_w2, wtb + W_ENC2, NH,  NL);
    transp_k<<<dim3(512/32, 512/32),tb>>>(qz0_w,  wtb + W_QZ0,  512, 512);
    transp_k<<<dim3(NH/32,  768/32),tb>>>(f_w1,   wtb + W_F1,   768, NH);
    transp_k<<<dim3(NL/32,  NH/32), tb>>>(f_w2,   wtb + W_F2,   NH,  NL);
    transp_k<<<dim3(NH/32,  NL/32), tb>>>(h_w1,   wtb + W_H1,   NL,  NH);
    transp_k<<<dim3(NL/32,  NH/32), tb>>>(h_w2,   wtb + W_H2,   NH,  NL);
    transp_k<<<dim3(ND/32,  NL/32), tb>>>(proj_w, wtb + W_PROJ, NL,  ND);
    copy_xs_k<<<(int)((size_t)M * ND / 256), 256>>>(xs, ctx, xst);

    GArgs zg{};

    // ---- encoder ----
    {
        GArgs a{xst, ND, wtb + W_ENC1, enc_b1, y1, NH, ND};
        gemm_bf<128,1,1,0><<<dim3(NH/128, M/128), 256, SMEM128>>>(a, a, M/128, nullptr, nullptr, nullptr);
    }
    {
        GArgs a{y1, NH, wtb + W_ENC2, enc_b2, ctx, 512, NH};
        gemm_bf<128,0,1,0><<<dim3(NL/128, M/128), 256, SMEM128>>>(a, a, M/128, nullptr, nullptr, nullptr);
    }

    // ---- q = ctx[:,0,:] @ qz0_w + qz0_b (fp32 out) ----
    {
        GArgs a{ctx, NT * 512, wtb + W_QZ0, qz0_b, q, 512, 512};
        gemm_bf<128,0,0,0><<<dim3(512/128, NB/128), 256, SMEM128>>>(a, a, NB/128, nullptr, nullptr, nullptr);
    }

    z0_k<<<NB, 256>>>(q, eps0, pz0_mean, pz0_logstd, z, zct, zs, kl0, dkl);
    diffv_k<<<1, NL>>>(gamma, diffv);
    copy_ct_k<<<(NB * 512) / 256, 256>>>(ctx, zct);

    // ---- scan: 63 steps, 3 launches each ----
    for (int t = 0; t < NT - 1; t++) {
        GArgs a0{zct, 768, wtb + W_F1, f_b1, hf, NH, 768};
        GArgs a1{zct, 768, wtb + W_H1, h_b1, hh, NH, NL};
        gemm_bf<128,1,1,0><<<dim3(NH/128, 2*(NB/128)), 256, SMEM128>>>(a0, a1, NB/128, nullptr, nullptr, nullptr);

        GArgs b0{hf, NH, wtb + W_F2, f_b2, drift, NL, NH};
        GArgs b1{hh, NH, wtb + W_H2, h_b2, prior, NL, NH};
        gemm_bf<32,0,0,0><<<dim3(NL/128, 2*(NB/32)), 256, SMEM32>>>(b0, b1, NB/32, nullptr, nullptr, nullptr);

        step_k<<<NB, 256>>>(t, ts, noise, ctx, z, zct, zs, drift, prior, diffv, dkl);
    }

    // ---- decoder fused with NLL reduction (xs read in fp32) ----
    {
        GArgs a{zs, NL, wtb + W_PROJ, proj_b, nullptr, ND, NL};
        gemm_bf<128,0,0,1><<<dim3(ND/128, M/128), 256, SMEM128>>>(a, zg, M/128, xs, noise_std, partials);
    }

    finalize_k<<<1, 256>>>(partials, (M/128) * (ND/128), dkl, kl0, noise_std, (float*)d_out);

    (void)in_sizes; (void)n_in; (void)out_size;
}